// round 16
// baseline (speedup 1.0000x reference)
#include <cuda_runtime.h>
#include <cuda_bf16.h>
#include <math.h>
#include <stdint.h>

#define T      4096
#define DH     64
#define NH     4
#define NB     64
#define DM     512
#define BHN    32
#define SELF_VAL (-5e4f)

__device__ float g_qk [(size_t)BHN * T * DH];
__device__ float g_v  [(size_t)BHN * T * DH];
__device__ int   g_st [BHN * NH * T];
__device__ float g_inv_norm[(size_t)BHN * T];
__device__ float g_o  [(size_t)BHN * NH * T * DH];
__device__ float g_lse[BHN * NH * T];
__device__ float g_ctx[(size_t)4 * T * DM];

// presplit bf16 operand planes (word = bf16x2 over a k-pair)
__device__ uint32_t g_qs[2][(size_t)16384 * 256];   // queries splits (hi, lo)
__device__ uint32_t g_cs[2][(size_t)16384 * 256];   // ctx splits
__device__ uint32_t g_wv [2][256 * 512];            // weights packed [k2][n]
__device__ uint32_t g_wo [2][256 * 512];

extern __shared__ float smem[];

// ---------------- packed fp32x2 helpers ----------------
__device__ __forceinline__ unsigned long long bcast2(float x) {
    unsigned long long r; asm("mov.b64 %0, {%1, %1};" : "=l"(r) : "f"(x)); return r;
}
__device__ __forceinline__ float2 unpk2(unsigned long long v) {
    float2 f; asm("mov.b64 {%0, %1}, %2;" : "=f"(f.x), "=f"(f.y) : "l"(v)); return f;
}
#define FMA2(d, a, b) asm("fma.rn.f32x2 %0, %1, %2, %0;" : "+l"(d) : "l"(a), "l"(b))

// ---------------- bf16 pack helpers ----------------
__device__ __forceinline__ uint32_t pkbf(float x, float y) {
    __nv_bfloat162 h = __float22bfloat162_rn(make_float2(x, y));
    return *(uint32_t*)&h;
}
__device__ __forceinline__ float2 upbf(uint32_t u) {
    __nv_bfloat162 h = *(__nv_bfloat162*)&u;
    return __bfloat1622float2(h);
}
__device__ __forceinline__ uint32_t smem_u32(const void* p) {
    uint32_t a;
    asm("{ .reg .u64 t; cvta.to.shared.u64 t, %1; cvt.u32.u64 %0, t; }" : "=r"(a) : "l"(p));
    return a;
}

#define MMA_BF16(c, a, b)                                                         \
    asm volatile("mma.sync.aligned.m16n8k16.row.col.f32.bf16.bf16.f32 "           \
                 "{%0,%1,%2,%3},{%4,%5,%6,%7},{%8,%9},{%0,%1,%2,%3};"             \
                 : "+f"(c[0]), "+f"(c[1]), "+f"(c[2]), "+f"(c[3])                 \
                 : "r"(a[0]), "r"(a[1]), "r"(a[2]), "r"(a[3]), "r"(b[0]), "r"(b[1]))

#define LDSM_X4(r0, r1, r2, r3, addr)                                             \
    asm volatile("ldmatrix.sync.aligned.m8n8.x4.shared.b16 {%0,%1,%2,%3}, [%4];"  \
                 : "=r"(r0), "=r"(r1), "=r"(r2), "=r"(r3) : "r"(addr))

// ---------------- fp32 GEMM (W_qk: EXACT — feeds hash argmax, must not perturb) ----
__global__ __launch_bounds__(256)
void gemm_qk_kernel(const float* __restrict__ A,
                    const float* __restrict__ Bm)
{
    const int N = 512, K = 512;
    __shared__ float As[2][16][132];
    __shared__ float Bs[2][16][68];

    int tid = threadIdx.x;
    int tx = tid & 15, ty = tid >> 4;
    int bm = blockIdx.y * 128, bn = blockIdx.x * 64;

    int f0 = tid * 2, f1 = tid * 2 + 1;
    int a_row0 = f0 >> 2, a_k0 = (f0 & 3) << 2;
    int a_row1 = f1 >> 2, a_k1 = (f1 & 3) << 2;
    int b_k = tid >> 4, b_n = (tid & 15) << 2;

    float4 ar0, ar1, br;
    unsigned long long acc2[8][2];
    #pragma unroll
    for (int i = 0; i < 8; i++) { acc2[i][0] = 0ull; acc2[i][1] = 0ull; }

#define LDG_TILE(k0)                                                              \
    {   ar0 = *(const float4*)&A[(size_t)(bm + a_row0) * K + (k0) + a_k0];        \
        ar1 = *(const float4*)&A[(size_t)(bm + a_row1) * K + (k0) + a_k1];        \
        br  = *(const float4*)&Bm[(size_t)((k0) + b_k) * N + bn + b_n]; }
#define STS_TILE(buf)                                                             \
    {   As[buf][a_k0 + 0][a_row0] = ar0.x; As[buf][a_k0 + 1][a_row0] = ar0.y;     \
        As[buf][a_k0 + 2][a_row0] = ar0.z; As[buf][a_k0 + 3][a_row0] = ar0.w;     \
        As[buf][a_k1 + 0][a_row1] = ar1.x; As[buf][a_k1 + 1][a_row1] = ar1.y;     \
        As[buf][a_k1 + 2][a_row1] = ar1.z; As[buf][a_k1 + 3][a_row1] = ar1.w;     \
        *(float4*)&Bs[buf][b_k][b_n] = br; }

    LDG_TILE(0); STS_TILE(0); __syncthreads();

    const int NST = K / 16;
    for (int s = 0; s < NST; s++) {
        if (s + 1 < NST) LDG_TILE((s + 1) * 16);
        int buf = s & 1;
        #pragma unroll
        for (int k = 0; k < 16; k++) {
            float4 a0 = *(const float4*)&As[buf][k][ty * 8];
            float4 a1 = *(const float4*)&As[buf][k][ty * 8 + 4];
            ulonglong2 b2 = *(const ulonglong2*)&Bs[buf][k][tx * 4];
            float av[8] = {a0.x, a0.y, a0.z, a0.w, a1.x, a1.y, a1.z, a1.w};
            #pragma unroll
            for (int i = 0; i < 8; i++) {
                unsigned long long ap = bcast2(av[i]);
                FMA2(acc2[i][0], ap, b2.x);
                FMA2(acc2[i][1], ap, b2.y);
            }
        }
        if (s + 1 < NST) STS_TILE((s + 1) & 1);
        __syncthreads();
    }

    #pragma unroll
    for (int i = 0; i < 8; i++) {
        int m = bm + ty * 8 + i;
        float2 p0 = unpk2(acc2[i][0]), p1 = unpk2(acc2[i][1]);
        float vv[4] = {p0.x, p0.y, p1.x, p1.y};
        #pragma unroll
        for (int j = 0; j < 4; j++) {
            int n = bn + tx * 4 + j;
            int b = m >> 12, t = m & 4095;
            int h = n >> 6,  d = n & 63;
            g_qk[(((size_t)(b * 8 + h)) * T + t) * DH + d] = vv[j];
        }
    }
#undef LDG_TILE
#undef STS_TILE
}

// ======== split kernels (run once per launch) ========
template <int TGT>   // 0: queries -> g_qs(2) ; 1: g_ctx -> g_cs(2)
__global__ void split_act_kernel(const float* __restrict__ src)
{
    size_t idx = (size_t)blockIdx.x * 256 + threadIdx.x;   // over 16384*256
    const float* sp = (TGT == 0) ? src : g_ctx;
    float2 v = *(const float2*)&sp[idx * 2];
    uint32_t h0 = pkbf(v.x, v.y);
    float2 f0 = upbf(h0);
    uint32_t h1 = pkbf(v.x - f0.x, v.y - f0.y);
    if (TGT == 0) { g_qs[0][idx] = h0; g_qs[1][idx] = h1; }
    else          { g_cs[0][idx] = h0; g_cs[1][idx] = h1; }
}

template <int TGT>   // 0: W_v ; 1: W_out
__global__ void split_w_kernel(const float* __restrict__ W)
{
    int idx = blockIdx.x * 256 + threadIdx.x;   // over 256*512
    int k2 = idx >> 9, n = idx & 511;
    float2 v = make_float2(W[(size_t)(2 * k2) * 512 + n],
                           W[(size_t)(2 * k2 + 1) * 512 + n]);
    uint32_t h0 = pkbf(v.x, v.y);
    float2 f0 = upbf(h0);
    uint32_t h1 = pkbf(v.x - f0.x, v.y - f0.y);
    if (TGT == 0) { g_wv[0][idx] = h0; g_wv[1][idx] = h1; }
    else          { g_wo[0][idx] = h0; g_wo[1][idx] = h1; }
}

// ======== presplit bf16x3 mma GEMM: C[16384,512] = A @ W ========
// MODE 1: A=g_qs B=g_wv -> g_v merged ; MODE 2: A=g_cs B=g_wo -> Cout + bias
#define GP_AW 4608      // words per A split tile [128][36]
#define GP_BW 4352      // words per B split tile [32][136]
#define SMEM_GP (2 * (GP_AW + GP_BW) * 4)

template <int MODE>
__global__ __launch_bounds__(256)
void gemm_pre_kernel(const float* __restrict__ bias, float* __restrict__ Cout)
{
    const uint32_t* A0 = (MODE == 1) ? g_qs[0] : g_cs[0];
    const uint32_t* A1 = (MODE == 1) ? g_qs[1] : g_cs[1];
    const uint32_t* B0 = (MODE == 1) ? g_wv[0] : g_wo[0];
    const uint32_t* B1 = (MODE == 1) ? g_wv[1] : g_wo[1];

    uint32_t* sA0 = (uint32_t*)smem;
    uint32_t* sA1 = sA0 + GP_AW;
    uint32_t* sB0 = sA1 + GP_AW;
    uint32_t* sB1 = sB0 + GP_BW;

    int tid = threadIdx.x, lane = tid & 31, wid = tid >> 5;
    int g = lane >> 2, tq = lane & 3;
    int wm = wid >> 1, wn = wid & 1;
    int m0 = wm * 32, n0 = wn * 64;
    int bm = blockIdx.y * 128, bn = blockIdx.x * 128;

    float acc[2][8][4] = {};

    for (int c = 0; c < 8; c++) {
        if (c > 0) __syncthreads();
        // A tiles: warp covers 16 rows, uint4 over 32 k-pair words
        #pragma unroll
        for (int i = 0; i < 4; i++) {
            int row = wid * 16 + i * 4 + (lane >> 3);
            int w4 = (lane & 7) * 4;
            size_t gofs = (size_t)(bm + row) * 256 + c * 32 + w4;
            *(uint4*)&sA0[row * 36 + w4] = *(const uint4*)&A0[gofs];
            *(uint4*)&sA1[row * 36 + w4] = *(const uint4*)&A1[gofs];
        }
        // B tiles: warp covers 4 k2 rows x 128 n-words
        #pragma unroll
        for (int j2 = 0; j2 < 4; j2++) {
            int k2 = wid * 4 + j2;
            size_t gofs = (size_t)(c * 32 + k2) * 512 + bn + lane * 4;
            *(uint4*)&sB0[k2 * 136 + lane * 4] = *(const uint4*)&B0[gofs];
            *(uint4*)&sB1[k2 * 136 + lane * 4] = *(const uint4*)&B1[gofs];
        }
        __syncthreads();

        #pragma unroll
        for (int ks = 0; ks < 4; ks++) {
            int kk = tq + 8 * ks;
            uint32_t ah[2][4], al[2][4];
            #pragma unroll
            for (int mi = 0; mi < 2; mi++) {
                int r0 = (m0 + mi * 16 + g) * 36;
                int r1 = (m0 + mi * 16 + g + 8) * 36;
                ah[mi][0] = sA0[r0 + kk];     ah[mi][1] = sA0[r1 + kk];
                ah[mi][2] = sA0[r0 + kk + 4]; ah[mi][3] = sA0[r1 + kk + 4];
                al[mi][0] = sA1[r0 + kk];     al[mi][1] = sA1[r1 + kk];
                al[mi][2] = sA1[r0 + kk + 4]; al[mi][3] = sA1[r1 + kk + 4];
            }
            #pragma unroll
            for (int ni = 0; ni < 8; ni++) {
                int n = n0 + ni * 8 + g;
                uint32_t bhv[2], blv[2];
                bhv[0] = sB0[kk * 136 + n]; bhv[1] = sB0[(kk + 4) * 136 + n];
                blv[0] = sB1[kk * 136 + n]; blv[1] = sB1[(kk + 4) * 136 + n];
                #pragma unroll
                for (int mi = 0; mi < 2; mi++) {
                    MMA_BF16(acc[mi][ni], ah[mi], bhv);
                    MMA_BF16(acc[mi][ni], ah[mi], blv);
                    MMA_BF16(acc[mi][ni], al[mi], bhv);
                }
            }
        }
    }

    #pragma unroll
    for (int mi = 0; mi < 2; mi++) {
        int m_top = bm + m0 + mi * 16 + g;
        #pragma unroll
        for (int ni = 0; ni < 8; ni++) {
            int n = bn + n0 + ni * 8 + 2 * tq;
            float c0 = acc[mi][ni][0], c1 = acc[mi][ni][1];
            float c2 = acc[mi][ni][2], c3 = acc[mi][ni][3];
            if (MODE == 2) {
                float2 bi2 = *(const float2*)&bias[n];
                *(float2*)&Cout[(size_t)m_top * 512 + n]       = make_float2(c0 + bi2.x, c1 + bi2.y);
                *(float2*)&Cout[(size_t)(m_top + 8) * 512 + n] = make_float2(c2 + bi2.x, c3 + bi2.y);
            } else {
                int h = n >> 6, d = n & 63;
                {
                    int b = m_top >> 12, tp = m_top & 4095;
                    *(float2*)&g_v[(((size_t)(b * 8 + h)) * T + tp) * DH + d] = make_float2(c0, c1);
                }
                {
                    int m2 = m_top + 8;
                    int b = m2 >> 12, tp = m2 & 4095;
                    *(float2*)&g_v[(((size_t)(b * 8 + h)) * T + tp) * DH + d] = make_float2(c2, c3);
                }
            }
        }
    }
}

// ======== hash + stable counting sort (+ key-norm precompute) ========
__global__ void hash_sort_kernel(const float* __restrict__ rotations)
{
    int bh = blockIdx.x >> 2, r = blockIdx.x & 3;
    __shared__ float rot[64][32];
    __shared__ unsigned char bucket[T];
    __shared__ int hist4[4][NB], offs[NB], tot[NB];
    int tid = threadIdx.x;
    for (int x = tid; x < 64 * 32; x += 256) {
        int d = x >> 5, i = x & 31;
        rot[d][i] = rotations[(d * NH + r) * 32 + i];
    }
    ((int*)hist4)[tid] = 0;
    __syncthreads();
    const float* qkbh = g_qk + (size_t)bh * T * DH;
    for (int t = tid; t < T; t += 256) {
        const float* q = qkbh + (size_t)t * DH;
        float s[32];
        float ss = 0.f;
        #pragma unroll
        for (int i = 0; i < 32; i++) s[i] = 0.f;
        for (int d4 = 0; d4 < 16; d4++) {
            float4 qv = *(const float4*)&q[d4 * 4];
            ss = fmaf(qv.x, qv.x, ss); ss = fmaf(qv.y, qv.y, ss);
            ss = fmaf(qv.z, qv.z, ss); ss = fmaf(qv.w, qv.w, ss);
            #pragma unroll
            for (int i = 0; i < 32; i++) {
                s[i] = fmaf(qv.x, rot[d4 * 4 + 0][i], s[i]);
                s[i] = fmaf(qv.y, rot[d4 * 4 + 1][i], s[i]);
                s[i] = fmaf(qv.z, rot[d4 * 4 + 2][i], s[i]);
                s[i] = fmaf(qv.w, rot[d4 * 4 + 3][i], s[i]);
            }
        }
        if (r == 0)
            g_inv_norm[(size_t)bh * T + t] = 1.0f / fmaxf(sqrtf(ss), 1e-12f);
        float best = -3.4e38f; int bi = 0;
        #pragma unroll
        for (int i = 0; i < 32; i++) { if (s[i] > best) { best = s[i]; bi = i; } }
        #pragma unroll
        for (int i = 0; i < 32; i++) { float v = -s[i]; if (v > best) { best = v; bi = 32 + i; } }
        bucket[t] = (unsigned char)bi;
        atomicAdd(&hist4[t >> 10][bi], 1);
    }
    __syncthreads();
    if (tid < NB)
        tot[tid] = hist4[0][tid] + hist4[1][tid] + hist4[2][tid] + hist4[3][tid];
    __syncthreads();
    if (tid == 0) {
        int run = 0;
        for (int b = 0; b < NB; b++) { offs[b] = run; run += tot[b]; }
    }
    __syncthreads();
    {
        int b = tid & 63, q = tid >> 6;
        int o = offs[b];
        #pragma unroll
        for (int qq = 0; qq < 3; qq++) if (qq < q) o += hist4[qq][b];
        int* stout = g_st + (bh * NH + r) * T;
        int t0 = q << 10;
        for (int t = t0; t < t0 + 1024; t++)
            if (bucket[t] == (unsigned char)b) stout[o++] = t;
    }
}

// ======== attention: 8 warps, split-column pairs, ldmatrix fragment loads ========
#define SMEM_ATTN2 ((2 * 128 * 36 + 2 * 64 * 68 + 512) * 4)

__global__ __launch_bounds__(256, 3)
void lsh_attn_mma_kernel()
{
    uint32_t* KbH = (uint32_t*)smem;
    uint32_t* KbL = KbH + 128 * 36;
    uint32_t* VtH = KbL + 128 * 36;
    uint32_t* VtL = VtH + 64 * 68;
    float* inv_norm = (float*)(VtL + 64 * 68);
    int*   kpos = (int*)(inv_norm + 128);
    float* pmax = (float*)(kpos + 128);
    float* psum = pmax + 128;
    float* Opart = (float*)KbH;

    int tid = threadIdx.x, lane = tid & 31, warp = tid >> 5;
    int g = lane >> 2, tq = lane & 3;
    int s = warp >> 1, h = warp & 1;
    int bh = blockIdx.x >> 8, c = blockIdx.x & 255;
    int r = c >> 6, pc = (c + 255) & 255;

    if (tid < 128) {
        int gi = (tid < 64) ? (c * 64 + tid) : (pc * 64 + tid - 64);
        int p = g_st[bh * (NH * T) + gi];
        kpos[tid] = p;
        inv_norm[tid] = g_inv_norm[(size_t)bh * T + p];
    }
    __syncthreads();

    for (int rr = 0; rr < 16; rr++) {
        int row = warp * 16 + rr;
        float2 f2 = ((const float2*)(g_qk + ((size_t)bh * T + kpos[row]) * DH))[lane];
        uint32_t hw = pkbf(f2.x, f2.y);
        KbH[row * 36 + lane] = hw;
        float2 hf = upbf(hw);
        KbL[row * 36 + lane] = pkbf(f2.x - hf.x, f2.y - hf.y);
    }
    for (int i = 0; i < 8; i++) {
        int k2v = warp * 8 + i;
        const float* va = g_v + ((size_t)bh * T + kpos[2 * k2v]) * DH;
        const float* vb = g_v + ((size_t)bh * T + kpos[2 * k2v + 1]) * DH;
        #pragma unroll
        for (int h2 = 0; h2 < 2; h2++) {
            int d = lane + 32 * h2;
            float2 f2 = make_float2(va[d], vb[d]);
            uint32_t hw = pkbf(f2.x, f2.y);
            VtH[d * 68 + k2v] = hw;
            float2 hf = upbf(hw);
            VtL[d * 68 + k2v] = pkbf(f2.x - hf.x, f2.y - hf.y);
        }
    }
    __syncthreads();

    int m0 = s * 16;
    int la = lane & 7, lb = (lane >> 3) & 1, lc = lane >> 4;
    uint32_t bKH = smem_u32(KbH), bKL = smem_u32(KbL);
    uint32_t bVH = smem_u32(VtH), bVL = smem_u32(VtL);
    uint32_t aoff = (uint32_t)(((m0 + la + 8 * lb) * 36 + 4 * lc) * 4);
    uint32_t boff[4];
    #pragma unroll
    for (int u = 0; u < 4; u++)
        boff[u] = (uint32_t)((((8 * h + 2 * u + lc) * 8 + la) * 36 + 4 * lb) * 4);
    uint32_t voff[4];
    #pragma unroll
    for (int u = 0; u < 4; u++)
        voff[u] = (uint32_t)((((2 * u + lc) * 8 + la) * 68 + 4 * lb) * 4);

    float acc[8][4];
    #pragma unroll
    for (int j = 0; j < 8; j++)
        #pragma unroll
        for (int x = 0; x < 4; x++) acc[j][x] = 0.f;

    #pragma unroll
    for (int kt = 0; kt < 4; kt++) {
        uint32_t ka = kt * 32;
        uint32_t ah[4], al[4];
        LDSM_X4(ah[0], ah[1], ah[2], ah[3], bKH + aoff + ka);
        LDSM_X4(al[0], al[1], al[2], al[3], bKL + aoff + ka);
        #pragma unroll
        for (int u = 0; u < 4; u++) {
            uint32_t bh4[4], bl4[4];
            LDSM_X4(bh4[0], bh4[1], bh4[2], bh4[3], bKH + boff[u] + ka);
            LDSM_X4(bl4[0], bl4[1], bl4[2], bl4[3], bKL + boff[u] + ka);
            uint32_t b0h[2] = {bh4[0], bh4[1]}, b1h[2] = {bh4[2], bh4[3]};
            uint32_t b0l[2] = {bl4[0], bl4[1]}, b1l[2] = {bl4[2], bl4[3]};
            MMA_BF16(acc[2 * u],     ah, b0h);
            MMA_BF16(acc[2 * u],     ah, b0l);
            MMA_BF16(acc[2 * u],     al, b0h);
            MMA_BF16(acc[2 * u + 1], ah, b1h);
            MMA_BF16(acc[2 * u + 1], ah, b1l);
            MMA_BF16(acc[2 * u + 1], al, b1h);
        }
    }

    int r0 = m0 + g, r1 = r0 + 8;
    int qp0 = kpos[r0], qp1 = kpos[r1];
    #pragma unroll
    for (int jj = 0; jj < 8; jj++) {
        int n = (8 * h + jj) * 8 + 2 * tq;
        float in0 = inv_norm[n], in1 = inv_norm[n + 1];
        int kc0 = kpos[n], kc1 = kpos[n + 1];
        acc[jj][0] = (kc0 == qp0) ? SELF_VAL : acc[jj][0] * in0 * 0.125f;
        acc[jj][1] = (kc1 == qp0) ? SELF_VAL : acc[jj][1] * in1 * 0.125f;
        acc[jj][2] = (kc0 == qp1) ? SELF_VAL : acc[jj][2] * in0 * 0.125f;
        acc[jj][3] = (kc1 == qp1) ? SELF_VAL : acc[jj][3] * in1 * 0.125f;
    }

    float mA = -3.4e38f, mB = -3.4e38f;
    #pragma unroll
    for (int jj = 0; jj < 8; jj++) {
        mA = fmaxf(mA, fmaxf(acc[jj][0], acc[jj][1]));
        mB = fmaxf(mB, fmaxf(acc[jj][2], acc[jj][3]));
    }
    mA = fmaxf(mA, __shfl_xor_sync(0xffffffffu, mA, 1));
    mA = fmaxf(mA, __shfl_xor_sync(0xffffffffu, mA, 2));
    mB = fmaxf(mB, __shfl_xor_sync(0xffffffffu, mB, 1));
    mB = fmaxf(mB, __shfl_xor_sync(0xffffffffu, mB, 2));
    if (tq == 0) {
        pmax[(s * 2 + h) * 16 + g]     = mA;
        pmax[(s * 2 + h) * 16 + g + 8] = mB;
    }
    __syncthreads();
    mA = fmaxf(mA, pmax[(s * 2 + (1 - h)) * 16 + g]);
    mB = fmaxf(mB, pmax[(s * 2 + (1 - h)) * 16 + g + 8]);

    float sA = 0.f, sB = 0.f;
    #pragma unroll
    for (int jj = 0; jj < 8; jj++) {
        acc[jj][0] = __expf(acc[jj][0] - mA); sA += acc[jj][0];
        acc[jj][1] = __expf(acc[jj][1] - mA); sA += acc[jj][1];
        acc[jj][2] = __expf(acc[jj][2] - mB); sB += acc[jj][2];
        acc[jj][3] = __expf(acc[jj][3] - mB); sB += acc[jj][3];
    }
    sA += __shfl_xor_sync(0xffffffffu, sA, 1);
    sA += __shfl_xor_sync(0xffffffffu, sA, 2);
    sB += __shfl_xor_sync(0xffffffffu, sB, 1);
    sB += __shfl_xor_sync(0xffffffffu, sB, 2);
    if (tq == 0) {
        psum[(s * 2 + h) * 16 + g]     = sA;
        psum[(s * 2 + h) * 16 + g + 8] = sB;
    }
    __syncthreads();
    sA += psum[(s * 2 + (1 - h)) * 16 + g];
    sB += psum[(s * 2 + (1 - h)) * 16 + g + 8];
    if (h == 0 && tq == 0) {
        size_t lb2 = ((size_t)bh * NH + r) * T;
        g_lse[lb2 + qp0] = mA + logf(sA);
        g_lse[lb2 + qp1] = mB + logf(sB);
    }
    float invA = 1.0f / sA, invB = 1.0f / sB;

    uint32_t Ph[4][4], Pl[4][4];
    #pragma unroll
    for (int t2 = 0; t2 < 4; t2++) {
        int j0 = 2 * t2, j1 = 2 * t2 + 1;
        Ph[t2][0] = pkbf(acc[j0][0], acc[j0][1]);
        Ph[t2][1] = pkbf(acc[j0][2], acc[j0][3]);
        Ph[t2][2] = pkbf(acc[j1][0], acc[j1][1]);
        Ph[t2][3] = pkbf(acc[j1][2], acc[j1][3]);
        float2 f;
        f = upbf(Ph[t2][0]); Pl[t2][0] = pkbf(acc[j0][0] - f.x, acc[j0][1] - f.y);
        f = upbf(Ph[t2][1]); Pl[t2][1] = pkbf(acc[j0][2] - f.x, acc[j0][3] - f.y);
        f = upbf(Ph[t2][2]); Pl[t2][2] = pkbf(acc[j1][0] - f.x, acc[j1][1] - f.y);
        f = upbf(Ph[t2][3]); Pl[t2][3] = pkbf(acc[j1][2] - f.x, acc[j1][3] - f.y);
    }

    float oacc[8][4];
    #pragma unroll
    for (int j = 0; j < 8; j++)
        #pragma unroll
        for (int x = 0; x < 4; x++) oacc[j][x] = 0.f;

    #pragma unroll
    for (int t2 = 0; t2 < 4; t2++) {
        uint32_t kofs = (uint32_t)((4 * h + t2) * 32);
        #pragma unroll
        for (int u = 0; u < 4; u++) {
            uint32_t vh4[4], vl4[4];
            LDSM_X4(vh4[0], vh4[1], vh4[2], vh4[3], bVH + voff[u] + kofs);
            LDSM_X4(vl4[0], vl4[1], vl4[2], vl4[3], bVL + voff[u] + kofs);
            uint32_t v0h[2] = {vh4[0], vh4[1]}, v1h[2] = {vh4[2], vh4[3]};
            uint32_t v0l[2] = {vl4[0], vl4[1]}, v1l[2] = {vl4[2], vl4[3]};
            MMA_BF16(oacc[2 * u],     Ph[t2], v0h);
            MMA_BF16(oacc[2 * u],     Ph[t2], v0l);
            MMA_BF16(oacc[2 * u],     Pl[t2], v0h);
            MMA_BF16(oacc[2 * u + 1], Ph[t2], v1h);
            MMA_BF16(oacc[2 * u + 1], Ph[t2], v1l);
            MMA_BF16(oacc[2 * u + 1], Pl[t2], v1h);
        }
    }

    if (h == 0) {
        float* op = Opart + s * (16 * 68);
        #pragma unroll
        for (int j2 = 0; j2 < 8; j2++) {
            int d0 = 8 * j2 + 2 * tq;
            *(float2*)&op[g * 68 + d0]       = make_float2(oacc[j2][0], oacc[j2][1]);
            *(float2*)&op[(g + 8) * 68 + d0] = make_float2(oacc[j2][2], oacc[j2][3]);
        }
    }
    __syncthreads();
    if (h == 1) {
        float* op = Opart + s * (16 * 68);
        size_t lb2 = ((size_t)bh * NH + r) * T;
        size_t b0 = (lb2 + qp0) * DH;
        size_t b1 = (lb2 + qp1) * DH;
        #pragma unroll
        for (int j2 = 0; j2 < 8; j2++) {
            int d0 = 8 * j2 + 2 * tq;
            float2 pa = *(float2*)&op[g * 68 + d0];
            float2 pb = *(float2*)&op[(g + 8) * 68 + d0];
            *(float2*)&g_o[b0 + d0] = make_float2((oacc[j2][0] + pa.x) * invA,
                                                  (oacc[j2][1] + pa.y) * invA);
            *(float2*)&g_o[b1 + d0] = make_float2((oacc[j2][2] + pb.x) * invB,
                                                  (oacc[j2][3] + pb.y) * invB);
        }
    }
}

// ======== combine ========
__global__ void combine_kernel()
{
    int idx = blockIdx.x * 256 + threadIdx.x;
    int d = idx & 63, pos = (idx >> 6) & 4095, bh = idx >> 18;
    float l[4];
    #pragma unroll
    for (int r = 0; r < 4; r++) l[r] = g_lse[((size_t)bh * 4 + r) * T + pos];
    float m = fmaxf(fmaxf(l[0], l[1]), fmaxf(l[2], l[3]));
    float w[4], ws = 0.f;
    #pragma unroll
    for (int r = 0; r < 4; r++) { w[r] = __expf(l[r] - m); ws += w[r]; }
    float o = 0.f;
    #pragma unroll
    for (int r = 0; r < 4; r++)
        o += w[r] * g_o[(((size_t)bh * 4 + r) * T + pos) * DH + d];
    o /= ws;
    int b = bh >> 3, h = bh & 7;
    g_ctx[((size_t)b * T + pos) * DM + h * 64 + d] = o;
}

// ======== launch ========
extern "C" void kernel_launch(void* const* d_in, const int* in_sizes, int n_in,
                              void* d_out, int out_size)
{
    (void)in_sizes; (void)n_in; (void)out_size;
    const float* queries   = (const float*)d_in[0];
    const float* W_qk      = (const float*)d_in[3];
    const float* W_v       = (const float*)d_in[4];
    const float* W_out     = (const float*)d_in[5];
    const float* b_out     = (const float*)d_in[6];
    const float* rotations = (const float*)d_in[7];
    float* out = (float*)d_out;

    static cudaStream_t s_aux = nullptr;
    static cudaEvent_t ev_fork = nullptr, ev_join = nullptr;
    if (!s_aux) {
        cudaStreamCreateWithFlags(&s_aux, cudaStreamNonBlocking);
        cudaEventCreateWithFlags(&ev_fork, cudaEventDisableTiming);
        cudaEventCreateWithFlags(&ev_join, cudaEventDisableTiming);
    }

    dim3 gq(512 / 64, 16384 / 128);    // fp32 qk gemm
    dim3 gp(512 / 128, 16384 / 128);   // presplit bf16 gemms

    cudaFuncSetAttribute(gemm_pre_kernel<1>, cudaFuncAttributeMaxDynamicSharedMemorySize, SMEM_GP);
    cudaFuncSetAttribute(gemm_pre_kernel<2>, cudaFuncAttributeMaxDynamicSharedMemorySize, SMEM_GP);
    cudaFuncSetAttribute(lsh_attn_mma_kernel, cudaFuncAttributeMaxDynamicSharedMemorySize, SMEM_ATTN2);

    // fork: aux does queries split + W_v split + W_v GEMM while main runs qk GEMM + hash
    cudaEventRecord(ev_fork, 0);
    cudaStreamWaitEvent(s_aux, ev_fork, 0);
    split_act_kernel<0><<<16384, 256, 0, s_aux>>>(queries);
    split_w_kernel<0><<<512, 256, 0, s_aux>>>(W_v);
    gemm_pre_kernel<1><<<gp, 256, SMEM_GP, s_aux>>>(nullptr, nullptr);
    cudaEventRecord(ev_join, s_aux);

    gemm_qk_kernel<<<gq, 256>>>(queries, W_qk);
    hash_sort_kernel<<<BHN * NH, 256>>>(rotations);
    split_w_kernel<1><<<512, 256>>>(W_out);

    cudaStreamWaitEvent(0, ev_join, 0);

    lsh_attn_mma_kernel<<<BHN * 256, 256, SMEM_ATTN2>>>();

    combine_kernel<<<(BHN * T * DH) / 256, 256>>>();
    split_act_kernel<1><<<16384, 256>>>(nullptr);

    gemm_pre_kernel<2><<<gp, 256, SMEM_GP>>>(b_out, out);
}

// round 17
// speedup vs baseline: 1.2137x; 1.2137x over previous
#include <cuda_runtime.h>
#include <cuda_bf16.h>
#include <math.h>
#include <stdint.h>

#define T      4096
#define DH     64
#define NH     4
#define NB     64
#define DM     512
#define BHN    32
#define SELF_VAL (-5e4f)

__device__ float g_qk [(size_t)BHN * T * DH];
__device__ float g_v  [(size_t)BHN * T * DH];
__device__ int   g_st [BHN * NH * T];
__device__ float g_inv_norm[(size_t)BHN * T];
__device__ float g_o  [(size_t)BHN * NH * T * DH];
__device__ float g_lse[BHN * NH * T];
__device__ float g_ctx[(size_t)4 * T * DM];
__device__ unsigned char g_bucket[(size_t)BHN * NH * T];

extern __shared__ float smem[];

// ---------------- packed fp32x2 helpers ----------------
__device__ __forceinline__ unsigned long long bcast2(float x) {
    unsigned long long r; asm("mov.b64 %0, {%1, %1};" : "=l"(r) : "f"(x)); return r;
}
__device__ __forceinline__ float2 unpk2(unsigned long long v) {
    float2 f; asm("mov.b64 {%0, %1}, %2;" : "=f"(f.x), "=f"(f.y) : "l"(v)); return f;
}
#define FMA2(d, a, b) asm("fma.rn.f32x2 %0, %1, %2, %0;" : "+l"(d) : "l"(a), "l"(b))

// ---------------- bf16 pack helpers ----------------
__device__ __forceinline__ uint32_t pkbf(float x, float y) {
    __nv_bfloat162 h = __float22bfloat162_rn(make_float2(x, y));
    return *(uint32_t*)&h;
}
__device__ __forceinline__ float2 upbf(uint32_t u) {
    __nv_bfloat162 h = *(__nv_bfloat162*)&u;
    return __bfloat1622float2(h);
}
__device__ __forceinline__ uint32_t smem_u32(const void* p) {
    uint32_t a;
    asm("{ .reg .u64 t; cvta.to.shared.u64 t, %1; cvt.u32.u64 %0, t; }" : "=r"(a) : "l"(p));
    return a;
}

#define MMA_BF16(c, a, b)                                                         \
    asm volatile("mma.sync.aligned.m16n8k16.row.col.f32.bf16.bf16.f32 "           \
                 "{%0,%1,%2,%3},{%4,%5,%6,%7},{%8,%9},{%0,%1,%2,%3};"             \
                 : "+f"(c[0]), "+f"(c[1]), "+f"(c[2]), "+f"(c[3])                 \
                 : "r"(a[0]), "r"(a[1]), "r"(a[2]), "r"(a[3]), "r"(b[0]), "r"(b[1]))

#define LDSM_X4(r0, r1, r2, r3, addr)                                             \
    asm volatile("ldmatrix.sync.aligned.m8n8.x4.shared.b16 {%0,%1,%2,%3}, [%4];"  \
                 : "=r"(r0), "=r"(r1), "=r"(r2), "=r"(r3) : "r"(addr))

// ---------------- fp32 GEMM (W_qk: EXACT — feeds hash argmax) ----------------
__global__ __launch_bounds__(256)
void gemm_qk_kernel(const float* __restrict__ A,
                    const float* __restrict__ Bm)
{
    const int N = 512, K = 512;
    __shared__ float As[2][16][132];
    __shared__ float Bs[2][16][68];

    int tid = threadIdx.x;
    int tx = tid & 15, ty = tid >> 4;
    int bm = blockIdx.y * 128, bn = blockIdx.x * 64;

    int f0 = tid * 2, f1 = tid * 2 + 1;
    int a_row0 = f0 >> 2, a_k0 = (f0 & 3) << 2;
    int a_row1 = f1 >> 2, a_k1 = (f1 & 3) << 2;
    int b_k = tid >> 4, b_n = (tid & 15) << 2;

    float4 ar0, ar1, br;
    unsigned long long acc2[8][2];
    #pragma unroll
    for (int i = 0; i < 8; i++) { acc2[i][0] = 0ull; acc2[i][1] = 0ull; }

#define LDG_TILE(k0)                                                              \
    {   ar0 = *(const float4*)&A[(size_t)(bm + a_row0) * K + (k0) + a_k0];        \
        ar1 = *(const float4*)&A[(size_t)(bm + a_row1) * K + (k0) + a_k1];        \
        br  = *(const float4*)&Bm[(size_t)((k0) + b_k) * N + bn + b_n]; }
#define STS_TILE(buf)                                                             \
    {   As[buf][a_k0 + 0][a_row0] = ar0.x; As[buf][a_k0 + 1][a_row0] = ar0.y;     \
        As[buf][a_k0 + 2][a_row0] = ar0.z; As[buf][a_k0 + 3][a_row0] = ar0.w;     \
        As[buf][a_k1 + 0][a_row1] = ar1.x; As[buf][a_k1 + 1][a_row1] = ar1.y;     \
        As[buf][a_k1 + 2][a_row1] = ar1.z; As[buf][a_k1 + 3][a_row1] = ar1.w;     \
        *(float4*)&Bs[buf][b_k][b_n] = br; }

    LDG_TILE(0); STS_TILE(0); __syncthreads();

    const int NST = K / 16;
    for (int s = 0; s < NST; s++) {
        if (s + 1 < NST) LDG_TILE((s + 1) * 16);
        int buf = s & 1;
        #pragma unroll
        for (int k = 0; k < 16; k++) {
            float4 a0 = *(const float4*)&As[buf][k][ty * 8];
            float4 a1 = *(const float4*)&As[buf][k][ty * 8 + 4];
            ulonglong2 b2 = *(const ulonglong2*)&Bs[buf][k][tx * 4];
            float av[8] = {a0.x, a0.y, a0.z, a0.w, a1.x, a1.y, a1.z, a1.w};
            #pragma unroll
            for (int i = 0; i < 8; i++) {
                unsigned long long ap = bcast2(av[i]);
                FMA2(acc2[i][0], ap, b2.x);
                FMA2(acc2[i][1], ap, b2.y);
            }
        }
        if (s + 1 < NST) STS_TILE((s + 1) & 1);
        __syncthreads();
    }

    #pragma unroll
    for (int i = 0; i < 8; i++) {
        int m = bm + ty * 8 + i;
        float2 p0 = unpk2(acc2[i][0]), p1 = unpk2(acc2[i][1]);
        float vv[4] = {p0.x, p0.y, p1.x, p1.y};
        #pragma unroll
        for (int j = 0; j < 4; j++) {
            int n = bn + tx * 4 + j;
            int b = m >> 12, t = m & 4095;
            int h = n >> 6,  d = n & 63;
            g_qk[(((size_t)(b * 8 + h)) * T + t) * DH + d] = vv[j];
        }
    }
#undef LDG_TILE
#undef STS_TILE
}

// ======== bf16 2-split mma.sync GEMM (W_v merged / W_out + bias) ========
#define PA 36
#define PB 136
#define AW (128 * PA)
#define BW (32 * PB)
#define SMEM_BF (2 * (AW + BW) * 4)

template <int MODE>   // 1: -> g_v merged ; 2: A=g_ctx, C = acc + bias
__global__ __launch_bounds__(256)
void gemm_bf16_kernel(const float* __restrict__ A, const float* __restrict__ W,
                      const float* __restrict__ bias, float* __restrict__ Cout)
{
    uint32_t* sA0 = (uint32_t*)smem;
    uint32_t* sA1 = sA0 + AW;
    uint32_t* sB0 = sA1 + AW;
    uint32_t* sB1 = sB0 + BW;

    int tid = threadIdx.x, lane = tid & 31, wid = tid >> 5;
    int g = lane >> 2, tq = lane & 3;
    int wm = wid >> 1, wn = wid & 1;
    int m0 = wm * 32, n0 = wn * 64;
    int bm = blockIdx.y * 128, bn = blockIdx.x * 128;
    const float* Ap = (MODE == 2) ? g_ctx : A;

    float acc[2][8][4] = {};

    for (int c = 0; c < 8; c++) {
        int k0 = c * 64;
        if (c > 0) __syncthreads();

        {
            int p = lane;
            #pragma unroll 4
            for (int rr = 0; rr < 16; rr++) {
                int row = wid * 16 + rr;
                float2 av = *(const float2*)&Ap[(size_t)(bm + row) * 512 + k0 + 2 * p];
                uint32_t h0 = pkbf(av.x, av.y);
                sA0[row * PA + p] = h0;
                float2 f0 = upbf(h0);
                sA1[row * PA + p] = pkbf(av.x - f0.x, av.y - f0.y);
            }
        }
        {
            int q = lane;
            #pragma unroll
            for (int j = 0; j < 4; j++) {
                int k2 = wid * 4 + j;
                const float* w0p = &W[(size_t)(k0 + 2 * k2) * 512 + bn];
                const float* w1p = &W[(size_t)(k0 + 2 * k2 + 1) * 512 + bn];
                #pragma unroll
                for (int u = 0; u < 4; u++) {
                    int n = q + 32 * u;
                    uint32_t h0 = pkbf(w0p[n], w1p[n]);
                    sB0[k2 * PB + n] = h0;
                    float2 f0 = upbf(h0);
                    sB1[k2 * PB + n] = pkbf(w0p[n] - f0.x, w1p[n] - f0.y);
                }
            }
        }
        __syncthreads();

        #pragma unroll
        for (int ks = 0; ks < 4; ks++) {
            int kk = tq + 8 * ks;
            uint32_t ah[2][4], al[2][4];
            #pragma unroll
            for (int mi = 0; mi < 2; mi++) {
                int r0 = (m0 + mi * 16 + g) * PA;
                int r1 = (m0 + mi * 16 + g + 8) * PA;
                ah[mi][0] = sA0[r0 + kk];     ah[mi][1] = sA0[r1 + kk];
                ah[mi][2] = sA0[r0 + kk + 4]; ah[mi][3] = sA0[r1 + kk + 4];
                al[mi][0] = sA1[r0 + kk];     al[mi][1] = sA1[r1 + kk];
                al[mi][2] = sA1[r0 + kk + 4]; al[mi][3] = sA1[r1 + kk + 4];
            }
            #pragma unroll
            for (int ni = 0; ni < 8; ni++) {
                int n = n0 + ni * 8 + g;
                uint32_t bhv[2], blv[2];
                bhv[0] = sB0[kk * PB + n]; bhv[1] = sB0[(kk + 4) * PB + n];
                blv[0] = sB1[kk * PB + n]; blv[1] = sB1[(kk + 4) * PB + n];
                #pragma unroll
                for (int mi = 0; mi < 2; mi++) {
                    MMA_BF16(acc[mi][ni], ah[mi], bhv);
                    MMA_BF16(acc[mi][ni], ah[mi], blv);
                    MMA_BF16(acc[mi][ni], al[mi], bhv);
                }
            }
        }
    }

    #pragma unroll
    for (int mi = 0; mi < 2; mi++) {
        int m_top = bm + m0 + mi * 16 + g;
        #pragma unroll
        for (int ni = 0; ni < 8; ni++) {
            int n = bn + n0 + ni * 8 + 2 * tq;
            float c0 = acc[mi][ni][0], c1 = acc[mi][ni][1];
            float c2 = acc[mi][ni][2], c3 = acc[mi][ni][3];
            if (MODE == 2) {
                float2 bi2 = *(const float2*)&bias[n];
                *(float2*)&Cout[(size_t)m_top * 512 + n]       = make_float2(c0 + bi2.x, c1 + bi2.y);
                *(float2*)&Cout[(size_t)(m_top + 8) * 512 + n] = make_float2(c2 + bi2.x, c3 + bi2.y);
            } else {
                int h = n >> 6, d = n & 63;
                {
                    int b = m_top >> 12, tp = m_top & 4095;
                    *(float2*)&g_v[(((size_t)(b * 8 + h)) * T + tp) * DH + d] = make_float2(c0, c1);
                }
                {
                    int m2 = m_top + 8;
                    int b = m2 >> 12, tp = m2 & 4095;
                    *(float2*)&g_v[(((size_t)(b * 8 + h)) * T + tp) * DH + d] = make_float2(c2, c3);
                }
            }
        }
    }
}

// ======== hash phase 1: rotations (FFMA2, bit-identical order) + buckets ========
// grid 512: (bh, r, quarter); fills all SMs
__global__ __launch_bounds__(256)
void hash_kernel(const float* __restrict__ rotations)
{
    int blk = blockIdx.x;
    int bh = blk >> 4, r = (blk >> 2) & 3, qt = blk & 3;
    __shared__ float rot[64][32];
    int tid = threadIdx.x;
    for (int x = tid; x < 64 * 32; x += 256) {
        int d = x >> 5, i = x & 31;
        rot[d][i] = rotations[(d * NH + r) * 32 + i];
    }
    __syncthreads();

    const float* qkbh = g_qk + (size_t)bh * T * DH;
    int t0 = qt << 10;
    for (int t = t0 + tid; t < t0 + 1024; t += 256) {
        const float* q = qkbh + (size_t)t * DH;
        unsigned long long s2[16];
        #pragma unroll
        for (int i = 0; i < 16; i++) s2[i] = 0ull;
        float ss = 0.f;
        for (int d4 = 0; d4 < 16; d4++) {
            float4 qv = *(const float4*)&q[d4 * 4];
            ss = fmaf(qv.x, qv.x, ss); ss = fmaf(qv.y, qv.y, ss);
            ss = fmaf(qv.z, qv.z, ss); ss = fmaf(qv.w, qv.w, ss);
            float comp[4] = {qv.x, qv.y, qv.z, qv.w};
            #pragma unroll
            for (int cc = 0; cc < 4; cc++) {
                unsigned long long qb = bcast2(comp[cc]);
                const ulonglong2* rp = (const ulonglong2*)&rot[d4 * 4 + cc][0];
                #pragma unroll
                for (int i4 = 0; i4 < 8; i4++) {
                    ulonglong2 rv = rp[i4];
                    FMA2(s2[2 * i4],     qb, rv.x);
                    FMA2(s2[2 * i4 + 1], qb, rv.y);
                }
            }
        }
        if (r == 0)
            g_inv_norm[(size_t)bh * T + t] = 1.0f / fmaxf(sqrtf(ss), 1e-12f);
        float s[32];
        #pragma unroll
        for (int i2 = 0; i2 < 16; i2++) {
            float2 p = unpk2(s2[i2]);
            s[2 * i2] = p.x; s[2 * i2 + 1] = p.y;
        }
        float best = -3.4e38f; int bi = 0;
        #pragma unroll
        for (int i = 0; i < 32; i++) { if (s[i] > best) { best = s[i]; bi = i; } }
        #pragma unroll
        for (int i = 0; i < 32; i++) { float v = -s[i]; if (v > best) { best = v; bi = 32 + i; } }
        g_bucket[((size_t)(bh * NH + r)) * T + t] = (unsigned char)bi;
    }
}

// ======== hash phase 2: stable counting sort ========
__global__ __launch_bounds__(256)
void sort_kernel()
{
    int bh = blockIdx.x >> 2, r = blockIdx.x & 3;
    __shared__ unsigned char bucket[T];
    __shared__ int hist4[4][NB], offs[NB], tot[NB];
    int tid = threadIdx.x;

    const uint32_t* bsrc = (const uint32_t*)(g_bucket + ((size_t)(bh * NH + r)) * T);
    for (int i = tid; i < T / 4; i += 256)
        ((uint32_t*)bucket)[i] = bsrc[i];
    ((int*)hist4)[tid] = 0;
    __syncthreads();
    for (int t = tid; t < T; t += 256)
        atomicAdd(&hist4[t >> 10][bucket[t]], 1);
    __syncthreads();
    if (tid < NB)
        tot[tid] = hist4[0][tid] + hist4[1][tid] + hist4[2][tid] + hist4[3][tid];
    __syncthreads();
    if (tid == 0) {
        int run = 0;
        for (int b = 0; b < NB; b++) { offs[b] = run; run += tot[b]; }
    }
    __syncthreads();
    {
        int b = tid & 63, q = tid >> 6;
        int o = offs[b];
        #pragma unroll
        for (int qq = 0; qq < 3; qq++) if (qq < q) o += hist4[qq][b];
        int* stout = g_st + (bh * NH + r) * T;
        int t0 = q << 10;
        for (int t = t0; t < t0 + 1024; t++)
            if (bucket[t] == (unsigned char)b) stout[o++] = t;
    }
}

// ======== attention: 8 warps, split-column pairs, ldmatrix fragment loads ========
#define SMEM_ATTN2 ((2 * 128 * 36 + 2 * 64 * 68 + 512) * 4)

__global__ __launch_bounds__(256, 3)
void lsh_attn_mma_kernel()
{
    uint32_t* KbH = (uint32_t*)smem;
    uint32_t* KbL = KbH + 128 * 36;
    uint32_t* VtH = KbL + 128 * 36;
    uint32_t* VtL = VtH + 64 * 68;
    float* inv_norm = (float*)(VtL + 64 * 68);
    int*   kpos = (int*)(inv_norm + 128);
    float* pmax = (float*)(kpos + 128);
    float* psum = pmax + 128;
    float* Opart = (float*)KbH;

    int tid = threadIdx.x, lane = tid & 31, warp = tid >> 5;
    int g = lane >> 2, tq = lane & 3;
    int s = warp >> 1, h = warp & 1;
    int bh = blockIdx.x >> 8, c = blockIdx.x & 255;
    int r = c >> 6, pc = (c + 255) & 255;

    if (tid < 128) {
        int gi = (tid < 64) ? (c * 64 + tid) : (pc * 64 + tid - 64);
        int p = g_st[bh * (NH * T) + gi];
        kpos[tid] = p;
        inv_norm[tid] = g_inv_norm[(size_t)bh * T + p];
    }
    __syncthreads();

    for (int rr = 0; rr < 16; rr++) {
        int row = warp * 16 + rr;
        float2 f2 = ((const float2*)(g_qk + ((size_t)bh * T + kpos[row]) * DH))[lane];
        uint32_t hw = pkbf(f2.x, f2.y);
        KbH[row * 36 + lane] = hw;
        float2 hf = upbf(hw);
        KbL[row * 36 + lane] = pkbf(f2.x - hf.x, f2.y - hf.y);
    }
    for (int i = 0; i < 8; i++) {
        int k2v = warp * 8 + i;
        const float* va = g_v + ((size_t)bh * T + kpos[2 * k2v]) * DH;
        const float* vb = g_v + ((size_t)bh * T + kpos[2 * k2v + 1]) * DH;
        #pragma unroll
        for (int h2 = 0; h2 < 2; h2++) {
            int d = lane + 32 * h2;
            float2 f2 = make_float2(va[d], vb[d]);
            uint32_t hw = pkbf(f2.x, f2.y);
            VtH[d * 68 + k2v] = hw;
            float2 hf = upbf(hw);
            VtL[d * 68 + k2v] = pkbf(f2.x - hf.x, f2.y - hf.y);
        }
    }
    __syncthreads();

    int m0 = s * 16;
    int la = lane & 7, lb = (lane >> 3) & 1, lc = lane >> 4;
    uint32_t bKH = smem_u32(KbH), bKL = smem_u32(KbL);
    uint32_t bVH = smem_u32(VtH), bVL = smem_u32(VtL);
    uint32_t aoff = (uint32_t)(((m0 + la + 8 * lb) * 36 + 4 * lc) * 4);
    uint32_t boff[4];
    #pragma unroll
    for (int u = 0; u < 4; u++)
        boff[u] = (uint32_t)((((8 * h + 2 * u + lc) * 8 + la) * 36 + 4 * lb) * 4);
    uint32_t voff[4];
    #pragma unroll
    for (int u = 0; u < 4; u++)
        voff[u] = (uint32_t)((((2 * u + lc) * 8 + la) * 68 + 4 * lb) * 4);

    float acc[8][4];
    #pragma unroll
    for (int j = 0; j < 8; j++)
        #pragma unroll
        for (int x = 0; x < 4; x++) acc[j][x] = 0.f;

    #pragma unroll
    for (int kt = 0; kt < 4; kt++) {
        uint32_t ka = kt * 32;
        uint32_t ah[4], al[4];
        LDSM_X4(ah[0], ah[1], ah[2], ah[3], bKH + aoff + ka);
        LDSM_X4(al[0], al[1], al[2], al[3], bKL + aoff + ka);
        #pragma unroll
        for (int u = 0; u < 4; u++) {
            uint32_t bh4[4], bl4[4];
            LDSM_X4(bh4[0], bh4[1], bh4[2], bh4[3], bKH + boff[u] + ka);
            LDSM_X4(bl4[0], bl4[1], bl4[2], bl4[3], bKL + boff[u] + ka);
            uint32_t b0h[2] = {bh4[0], bh4[1]}, b1h[2] = {bh4[2], bh4[3]};
            uint32_t b0l[2] = {bl4[0], bl4[1]}, b1l[2] = {bl4[2], bl4[3]};
            MMA_BF16(acc[2 * u],     ah, b0h);
            MMA_BF16(acc[2 * u],     ah, b0l);
            MMA_BF16(acc[2 * u],     al, b0h);
            MMA_BF16(acc[2 * u + 1], ah, b1h);
            MMA_BF16(acc[2 * u + 1], ah, b1l);
            MMA_BF16(acc[2 * u + 1], al, b1h);
        }
    }

    int r0 = m0 + g, r1 = r0 + 8;
    int qp0 = kpos[r0], qp1 = kpos[r1];
    #pragma unroll
    for (int jj = 0; jj < 8; jj++) {
        int n = (8 * h + jj) * 8 + 2 * tq;
        float in0 = inv_norm[n], in1 = inv_norm[n + 1];
        int kc0 = kpos[n], kc1 = kpos[n + 1];
        acc[jj][0] = (kc0 == qp0) ? SELF_VAL : acc[jj][0] * in0 * 0.125f;
        acc[jj][1] = (kc1 == qp0) ? SELF_VAL : acc[jj][1] * in1 * 0.125f;
        acc[jj][2] = (kc0 == qp1) ? SELF_VAL : acc[jj][2] * in0 * 0.125f;
        acc[jj][3] = (kc1 == qp1) ? SELF_VAL : acc[jj][3] * in1 * 0.125f;
    }

    float mA = -3.4e38f, mB = -3.4e38f;
    #pragma unroll
    for (int jj = 0; jj < 8; jj++) {
        mA = fmaxf(mA, fmaxf(acc[jj][0], acc[jj][1]));
        mB = fmaxf(mB, fmaxf(acc[jj][2], acc[jj][3]));
    }
    mA = fmaxf(mA, __shfl_xor_sync(0xffffffffu, mA, 1));
    mA = fmaxf(mA, __shfl_xor_sync(0xffffffffu, mA, 2));
    mB = fmaxf(mB, __shfl_xor_sync(0xffffffffu, mB, 1));
    mB = fmaxf(mB, __shfl_xor_sync(0xffffffffu, mB, 2));
    if (tq == 0) {
        pmax[(s * 2 + h) * 16 + g]     = mA;
        pmax[(s * 2 + h) * 16 + g + 8] = mB;
    }
    __syncthreads();
    mA = fmaxf(mA, pmax[(s * 2 + (1 - h)) * 16 + g]);
    mB = fmaxf(mB, pmax[(s * 2 + (1 - h)) * 16 + g + 8]);

    float sA = 0.f, sB = 0.f;
    #pragma unroll
    for (int jj = 0; jj < 8; jj++) {
        acc[jj][0] = __expf(acc[jj][0] - mA); sA += acc[jj][0];
        acc[jj][1] = __expf(acc[jj][1] - mA); sA += acc[jj][1];
        acc[jj][2] = __expf(acc[jj][2] - mB); sB += acc[jj][2];
        acc[jj][3] = __expf(acc[jj][3] - mB); sB += acc[jj][3];
    }
    sA += __shfl_xor_sync(0xffffffffu, sA, 1);
    sA += __shfl_xor_sync(0xffffffffu, sA, 2);
    sB += __shfl_xor_sync(0xffffffffu, sB, 1);
    sB += __shfl_xor_sync(0xffffffffu, sB, 2);
    if (tq == 0) {
        psum[(s * 2 + h) * 16 + g]     = sA;
        psum[(s * 2 + h) * 16 + g + 8] = sB;
    }
    __syncthreads();
    sA += psum[(s * 2 + (1 - h)) * 16 + g];
    sB += psum[(s * 2 + (1 - h)) * 16 + g + 8];
    if (h == 0 && tq == 0) {
        size_t lb2 = ((size_t)bh * NH + r) * T;
        g_lse[lb2 + qp0] = mA + logf(sA);
        g_lse[lb2 + qp1] = mB + logf(sB);
    }
    float invA = 1.0f / sA, invB = 1.0f / sB;

    uint32_t Ph[4][4], Pl[4][4];
    #pragma unroll
    for (int t2 = 0; t2 < 4; t2++) {
        int j0 = 2 * t2, j1 = 2 * t2 + 1;
        Ph[t2][0] = pkbf(acc[j0][0], acc[j0][1]);
        Ph[t2][1] = pkbf(acc[j0][2], acc[j0][3]);
        Ph[t2][2] = pkbf(acc[j1][0], acc[j1][1]);
        Ph[t2][3] = pkbf(acc[j1][2], acc[j1][3]);
        float2 f;
        f = upbf(Ph[t2][0]); Pl[t2][0] = pkbf(acc[j0][0] - f.x, acc[j0][1] - f.y);
        f = upbf(Ph[t2][1]); Pl[t2][1] = pkbf(acc[j0][2] - f.x, acc[j0][3] - f.y);
        f = upbf(Ph[t2][2]); Pl[t2][2] = pkbf(acc[j1][0] - f.x, acc[j1][1] - f.y);
        f = upbf(Ph[t2][3]); Pl[t2][3] = pkbf(acc[j1][2] - f.x, acc[j1][3] - f.y);
    }

    float oacc[8][4];
    #pragma unroll
    for (int j = 0; j < 8; j++)
        #pragma unroll
        for (int x = 0; x < 4; x++) oacc[j][x] = 0.f;

    #pragma unroll
    for (int t2 = 0; t2 < 4; t2++) {
        uint32_t kofs = (uint32_t)((4 * h + t2) * 32);
        #pragma unroll
        for (int u = 0; u < 4; u++) {
            uint32_t vh4[4], vl4[4];
            LDSM_X4(vh4[0], vh4[1], vh4[2], vh4[3], bVH + voff[u] + kofs);
            LDSM_X4(vl4[0], vl4[1], vl4[2], vl4[3], bVL + voff[u] + kofs);
            uint32_t v0h[2] = {vh4[0], vh4[1]}, v1h[2] = {vh4[2], vh4[3]};
            uint32_t v0l[2] = {vl4[0], vl4[1]}, v1l[2] = {vl4[2], vl4[3]};
            MMA_BF16(oacc[2 * u],     Ph[t2], v0h);
            MMA_BF16(oacc[2 * u],     Ph[t2], v0l);
            MMA_BF16(oacc[2 * u],     Pl[t2], v0h);
            MMA_BF16(oacc[2 * u + 1], Ph[t2], v1h);
            MMA_BF16(oacc[2 * u + 1], Ph[t2], v1l);
            MMA_BF16(oacc[2 * u + 1], Pl[t2], v1h);
        }
    }

    if (h == 0) {
        float* op = Opart + s * (16 * 68);
        #pragma unroll
        for (int j2 = 0; j2 < 8; j2++) {
            int d0 = 8 * j2 + 2 * tq;
            *(float2*)&op[g * 68 + d0]       = make_float2(oacc[j2][0], oacc[j2][1]);
            *(float2*)&op[(g + 8) * 68 + d0] = make_float2(oacc[j2][2], oacc[j2][3]);
        }
    }
    __syncthreads();
    if (h == 1) {
        float* op = Opart + s * (16 * 68);
        size_t lb2 = ((size_t)bh * NH + r) * T;
        size_t b0 = (lb2 + qp0) * DH;
        size_t b1 = (lb2 + qp1) * DH;
        #pragma unroll
        for (int j2 = 0; j2 < 8; j2++) {
            int d0 = 8 * j2 + 2 * tq;
            float2 pa = *(float2*)&op[g * 68 + d0];
            float2 pb = *(float2*)&op[(g + 8) * 68 + d0];
            *(float2*)&g_o[b0 + d0] = make_float2((oacc[j2][0] + pa.x) * invA,
                                                  (oacc[j2][1] + pa.y) * invA);
            *(float2*)&g_o[b1 + d0] = make_float2((oacc[j2][2] + pb.x) * invB,
                                                  (oacc[j2][3] + pb.y) * invB);
        }
    }
}

// ======== combine ========
__global__ void combine_kernel()
{
    int idx = blockIdx.x * 256 + threadIdx.x;
    int d = idx & 63, pos = (idx >> 6) & 4095, bh = idx >> 18;
    float l[4];
    #pragma unroll
    for (int r = 0; r < 4; r++) l[r] = g_lse[((size_t)bh * 4 + r) * T + pos];
    float m = fmaxf(fmaxf(l[0], l[1]), fmaxf(l[2], l[3]));
    float w[4], ws = 0.f;
    #pragma unroll
    for (int r = 0; r < 4; r++) { w[r] = __expf(l[r] - m); ws += w[r]; }
    float o = 0.f;
    #pragma unroll
    for (int r = 0; r < 4; r++)
        o += w[r] * g_o[(((size_t)bh * 4 + r) * T + pos) * DH + d];
    o /= ws;
    int b = bh >> 3, h = bh & 7;
    g_ctx[((size_t)b * T + pos) * DM + h * 64 + d] = o;
}

// ======== launch ========
extern "C" void kernel_launch(void* const* d_in, const int* in_sizes, int n_in,
                              void* d_out, int out_size)
{
    (void)in_sizes; (void)n_in; (void)out_size;
    const float* queries   = (const float*)d_in[0];
    const float* W_qk      = (const float*)d_in[3];
    const float* W_v       = (const float*)d_in[4];
    const float* W_out     = (const float*)d_in[5];
    const float* b_out     = (const float*)d_in[6];
    const float* rotations = (const float*)d_in[7];
    float* out = (float*)d_out;

    static cudaStream_t s_aux = nullptr;
    static cudaEvent_t ev_fork = nullptr, ev_join = nullptr;
    if (!s_aux) {
        cudaStreamCreateWithFlags(&s_aux, cudaStreamNonBlocking);
        cudaEventCreateWithFlags(&ev_fork, cudaEventDisableTiming);
        cudaEventCreateWithFlags(&ev_join, cudaEventDisableTiming);
    }

    dim3 gq(512 / 64, 16384 / 128);
    dim3 gb(512 / 128, 16384 / 128);

    cudaFuncSetAttribute(gemm_bf16_kernel<1>, cudaFuncAttributeMaxDynamicSharedMemorySize, SMEM_BF);
    cudaFuncSetAttribute(gemm_bf16_kernel<2>, cudaFuncAttributeMaxDynamicSharedMemorySize, SMEM_BF);
    cudaFuncSetAttribute(lsh_attn_mma_kernel, cudaFuncAttributeMaxDynamicSharedMemorySize, SMEM_ATTN2);

    cudaEventRecord(ev_fork, 0);
    cudaStreamWaitEvent(s_aux, ev_fork, 0);
    gemm_bf16_kernel<1><<<gb, 256, SMEM_BF, s_aux>>>(queries, W_v, nullptr, nullptr);
    cudaEventRecord(ev_join, s_aux);

    gemm_qk_kernel<<<gq, 256>>>(queries, W_qk);
    hash_kernel<<<BHN * NH * 4, 256>>>(rotations);
    sort_kernel<<<BHN * NH, 256>>>();

    cudaStreamWaitEvent(0, ev_join, 0);

    lsh_attn_mma_kernel<<<BHN * 256, 256, SMEM_ATTN2>>>();

    combine_kernel<<<(BHN * T * DH) / 256, 256>>>();

    gemm_bf16_kernel<2><<<gb, 256, SMEM_BF>>>(nullptr, W_out, b_out, out);
}